// round 16
// baseline (speedup 1.0000x reference)
#include <cuda_runtime.h>

#define NB 512
#define LL 2713
#define ZZ 58
#define GG 8
#define FFD 2048
#define NLY 6
#define RNAIN 1018
#define L1D 256
#define L2D 64
#define CATD 528
#define NPAIR 14848   // 29696 rows / 2
#define NJB 16        // j chunks (128 j each)
#define LHALF 1360    // embed L-split

typedef unsigned long long u64;

// -------- scratch (device globals; no allocations allowed) --------
__device__ float g_r1[NB * L1D];
__device__ float g_r[NB * L2D];
__device__ float g_x[NB * ZZ * GG];
__device__ float g_epart[2][NB][ZZ * GG];      // embed partials per L-half
__device__ float g_chemt[LL * GG];             // chem_w transposed [l][g]
__device__ float g_wpk[NLY * FFD * 36];        // per j: w1-dup x16 | w2-dup x16 | b1-dup x2 | pad2
__device__ float g_l1t[RNAIN * L1D];           // lin1_w transposed [k][j]
__device__ float g_c1t[CATD * 64];             // c1_w transposed [k][j]
__device__ u64   g_part64[NJB * NPAIR * 8];    // ffn partials [jb][pair][o] as f32x2

// -------- packed f32x2 helpers (FFMA2 path ptxas won't emit from C++) ------
__device__ __forceinline__ u64 pk2(float lo, float hi) {
    u64 d; asm("mov.b64 %0,{%1,%2};" : "=l"(d) : "f"(lo), "f"(hi)); return d;
}
__device__ __forceinline__ void upk2(u64 d, float& lo, float& hi) {
    asm("mov.b64 {%0,%1},%2;" : "=f"(lo), "=f"(hi) : "l"(d));
}
__device__ __forceinline__ u64 ffma2(u64 a, u64 b, u64 c) {
    u64 d; asm("fma.rn.f32x2 %0,%1,%2,%3;" : "=l"(d) : "l"(a), "l"(b), "l"(c)); return d;
}
__device__ __forceinline__ u64 fadd2(u64 a, u64 b) {
    u64 d; asm("add.rn.f32x2 %0,%1,%2;" : "=l"(d) : "l"(a), "l"(b)); return d;
}
__device__ __forceinline__ u64 relu2(u64 a) {
    float h0, h1; upk2(a, h0, h1);
    return pk2(fmaxf(h0, 0.f), fmaxf(h1, 0.f));
}

// -------- prep: transposes / weight packing (cheap, once per graph) --------
#define PREP_N0 (LL * GG)
#define PREP_N1 (NLY * FFD * 36)
#define PREP_N2 (RNAIN * L1D)
#define PREP_N3 (CATD * 64)
__global__ void prep_kernel(const float* __restrict__ chem_w,
                            const float* __restrict__ ff1_w,
                            const float* __restrict__ ff1_b,
                            const float* __restrict__ ff2_w,
                            const float* __restrict__ lin1_w,
                            const float* __restrict__ c1_w) {
    int i = blockIdx.x * blockDim.x + threadIdx.x;
    if (i < PREP_N0) {
        int l = i / GG, g = i % GG;
        g_chemt[i] = chem_w[g * LL + l];
    }
    int n = i - PREP_N0;
    if (n >= 0 && n < PREP_N1) {
        int ly = n / (FFD * 36);
        int rem = n % (FFD * 36);
        int j = rem / 36, s = rem % 36;
        float v = 0.f;
        if (s < 16)      v = ff1_w[(ly * FFD + j) * GG + (s >> 1)];
        else if (s < 32) v = ff2_w[(ly * GG + ((s - 16) >> 1)) * FFD + j];
        else if (s < 34) v = ff1_b[ly * FFD + j];
        g_wpk[n] = v;
    }
    int n2 = n - PREP_N1;
    if (n2 >= 0 && n2 < PREP_N2) {
        int k = n2 / L1D, j = n2 % L1D;
        g_l1t[n2] = lin1_w[j * RNAIN + k];
    }
    int n3 = n2 - PREP_N2;
    if (n3 >= 0 && n3 < PREP_N3) {
        int k = n3 / 64, j = n3 % 64;
        g_c1t[n3] = c1_w[j * CATD + k];
    }
}

// -------- rna branch (coalesced via transposed weights) --------
__global__ void rna1_kernel(const float* __restrict__ rna,
                            const float* __restrict__ bias) {
    __shared__ float xs[8][RNAIN];
    int b0 = blockIdx.x * 8;
    for (int i = threadIdx.x; i < 8 * RNAIN; i += 256)
        (&xs[0][0])[i] = rna[b0 * RNAIN + i];
    __syncthreads();
    int j = threadIdx.x;
    float acc[8];
#pragma unroll
    for (int r = 0; r < 8; r++) acc[r] = 0.f;
#pragma unroll 2
    for (int k = 0; k < RNAIN; k++) {
        float wv = g_l1t[k * L1D + j];
#pragma unroll
        for (int r = 0; r < 8; r++) acc[r] += xs[r][k] * wv;
    }
    float bv = bias[j];
#pragma unroll
    for (int r = 0; r < 8; r++) g_r1[(b0 + r) * L1D + j] = acc[r] + bv;
}

__global__ void rna2_kernel(const float* __restrict__ w,
                            const float* __restrict__ bias) {
    __shared__ float xs[8][L1D];
    int b0 = blockIdx.x * 8;
    for (int i = threadIdx.x; i < 8 * L1D; i += 64)
        (&xs[0][0])[i] = g_r1[b0 * L1D + i];
    __syncthreads();
    int j = threadIdx.x;
    float acc[8];
#pragma unroll
    for (int r = 0; r < 8; r++) acc[r] = 0.f;
    const float* wr = w + j * L1D;
#pragma unroll 4
    for (int k = 0; k < L1D; k++) {
        float wv = wr[k];
#pragma unroll
        for (int r = 0; r < 8; r++) acc[r] += xs[r][k] * wv;
    }
    float bv = bias[j];
#pragma unroll
    for (int r = 0; r < 8; r++) g_r[(b0 + r) * L2D + j] = acc[r] + bv;
}

// -------- embedding: split-L (grid NB x 2), depth-8 batched loads ---------
__global__ __launch_bounds__(512, 2) void embed_kernel(const float* __restrict__ drug) {
    __shared__ float red[8][ZZ * GG];
    int b = blockIdx.x, half = blockIdx.y, tid = threadIdx.x;
    int warp = tid >> 5, lane = tid & 31;
    const float* dbase = drug + (long)b * (LL * ZZ);
    int lbase = half * LHALF;
    int lend = (half == 0) ? LHALF : LL;
    bool act = lane < 29;
    int zoff = act ? 2 * lane : 54;
    u64 acc[2][4];
#pragma unroll
    for (int zi = 0; zi < 2; zi++)
#pragma unroll
        for (int gp = 0; gp < 4; gp++) acc[zi][gp] = 0ull;

    for (int it = 0; it < 10; it++) {
        int l0 = lbase + warp + 128 * it;
        float2 d[8];
#pragma unroll
        for (int k = 0; k < 8; k++)
            d[k] = *(const float2*)(dbase + (l0 + 16 * k) * ZZ + zoff);
#pragma unroll
        for (int k = 0; k < 8; k++) {
            const ulonglong2* crow = (const ulonglong2*)(g_chemt + (l0 + 16 * k) * GG);
            ulonglong2 cA = crow[0], cB = crow[1];
            u64 d0 = pk2(d[k].x, d[k].x), d1 = pk2(d[k].y, d[k].y);
            acc[0][0] = ffma2(cA.x, d0, acc[0][0]);
            acc[0][1] = ffma2(cA.y, d0, acc[0][1]);
            acc[0][2] = ffma2(cB.x, d0, acc[0][2]);
            acc[0][3] = ffma2(cB.y, d0, acc[0][3]);
            acc[1][0] = ffma2(cA.x, d1, acc[1][0]);
            acc[1][1] = ffma2(cA.y, d1, acc[1][1]);
            acc[1][2] = ffma2(cB.x, d1, acc[1][2]);
            acc[1][3] = ffma2(cB.y, d1, acc[1][3]);
        }
    }
    for (int l = lbase + 1280 + warp; l < lend; l += 16) {
        float2 d = *(const float2*)(dbase + l * ZZ + zoff);
        const ulonglong2* crow = (const ulonglong2*)(g_chemt + l * GG);
        ulonglong2 cA = crow[0], cB = crow[1];
        u64 d0 = pk2(d.x, d.x), d1 = pk2(d.y, d.y);
        acc[0][0] = ffma2(cA.x, d0, acc[0][0]);
        acc[0][1] = ffma2(cA.y, d0, acc[0][1]);
        acc[0][2] = ffma2(cB.x, d0, acc[0][2]);
        acc[0][3] = ffma2(cB.y, d0, acc[0][3]);
        acc[1][0] = ffma2(cA.x, d1, acc[1][0]);
        acc[1][1] = ffma2(cA.y, d1, acc[1][1]);
        acc[1][2] = ffma2(cB.x, d1, acc[1][2]);
        acc[1][3] = ffma2(cB.y, d1, acc[1][3]);
    }
    if (warp >= 8 && act) {
#pragma unroll
        for (int zi = 0; zi < 2; zi++)
#pragma unroll
            for (int gp = 0; gp < 4; gp++)
                *(u64*)&red[warp - 8][(2 * lane + zi) * GG + 2 * gp] = acc[zi][gp];
    }
    __syncthreads();
    if (warp < 8 && act) {
#pragma unroll
        for (int zi = 0; zi < 2; zi++)
#pragma unroll
            for (int gp = 0; gp < 4; gp++)
                acc[zi][gp] = fadd2(acc[zi][gp], *(u64*)&red[warp][(2 * lane + zi) * GG + 2 * gp]);
    }
    __syncthreads();
    if (warp < 8 && act) {
#pragma unroll
        for (int zi = 0; zi < 2; zi++)
#pragma unroll
            for (int gp = 0; gp < 4; gp++)
                *(u64*)&red[warp][(2 * lane + zi) * GG + 2 * gp] = acc[zi][gp];
    }
    __syncthreads();
    if (tid < ZZ * GG) {
        float s = 0.f;
#pragma unroll
        for (int w = 0; w < 8; w++) s += red[w][tid];
        g_epart[half][b][tid] = s;
    }
}

// -------- attention layer: [finalize prev FFN / embed] + qkv + softmax ----
__global__ __launch_bounds__(256) void attn_kernel(const float* __restrict__ qkv_w,
                            const float* __restrict__ qkv_b,
                            const float* __restrict__ out_w,
                            const float* __restrict__ out_b,
                            const float* __restrict__ ln_g,
                            const float* __restrict__ ln_b,
                            const float* __restrict__ ff2_b,
                            const float* __restrict__ ln2_g,
                            const float* __restrict__ ln2_b,
                            const float* __restrict__ pos_w, int layer) {
    qkv_w += layer * 24 * GG; qkv_b += layer * 24;
    out_w += layer * GG * GG; out_b += layer * GG;
    ln_g += layer * GG; ln_b += layer * GG;
    __shared__ float xs[ZZ * GG], qs[ZZ * GG], os_[ZZ * GG];
    __shared__ float2 kv[ZZ * GG];
    __shared__ float wqkvT[GG * 24], bqkv[24], wout[GG * GG], bout[GG], lng[GG], lnb[GG];
    __shared__ float kmax[GG], kmin[GG];
    int b = blockIdx.x, tid = threadIdx.x;
    if (tid < 192) { int j = tid / 8, kk = tid % 8; wqkvT[kk * 24 + j] = qkv_w[tid]; }
    if (tid < 24) bqkv[tid] = qkv_b[tid];
    if (tid < 64) wout[tid] = out_w[tid];
    if (tid < 8) { bout[tid] = out_b[tid]; lng[tid] = ln_g[tid]; lnb[tid] = ln_b[tid]; }

    if (layer > 0) {
        const float* fb  = ff2_b + (layer - 1) * GG;
        const float* gp  = (const float*)g_part64;
        for (int i = tid; i < ZZ * GG; i += 256) {
            int s = i >> 3, o = i & 7;
            int p = b * 29 + (s >> 1), half = s & 1;
            float v = fb[o] + g_x[b * (ZZ * GG) + i];
#pragma unroll
            for (int jb = 0; jb < NJB; jb++)
                v += gp[(((size_t)jb * NPAIR + p) * 8 + o) * 2 + half];
            xs[i] = v;
        }
        __syncthreads();
        const float* lg2 = ln2_g + (layer - 1) * GG;
        const float* lb2 = ln2_b + (layer - 1) * GG;
        if (tid < ZZ) {
            float* pr = xs + tid * 8;
            float mu = 0.f;
#pragma unroll
            for (int g = 0; g < 8; g++) mu += pr[g];
            mu *= 0.125f;
            float var = 0.f;
#pragma unroll
            for (int g = 0; g < 8; g++) { float d = pr[g] - mu; var += d * d; }
            var *= 0.125f;
            float inv = rsqrtf(var + 1e-5f);
#pragma unroll
            for (int g = 0; g < 8; g++) pr[g] = (pr[g] - mu) * inv * lg2[g] + lb2[g];
        }
    } else {
        for (int i = tid; i < ZZ * GG; i += 256) {
            int z = i >> 3, g = i & 7;
            xs[i] = g_epart[0][b][i] + g_epart[1][b][i] + pos_w[g * ZZ + z];
        }
    }
    __syncthreads();
    for (int i = tid; i < ZZ * 24; i += 256) {
        int zz = i / 24, j = i % 24;
        float a = bqkv[j];
#pragma unroll
        for (int kk = 0; kk < 8; kk++) a += xs[zz * 8 + kk] * wqkvT[kk * 24 + j];
        if (j < 8) qs[zz * 8 + j] = a;
        else if (j < 16) kv[zz * 8 + (j - 8)].x = a;
        else kv[zz * 8 + (j - 16)].y = a;
    }
    __syncthreads();
    if (tid < 8) {
        float mx = -1e30f, mn = 1e30f;
        for (int t = 0; t < ZZ; t++) {
            float k = kv[t * 8 + tid].x;
            mx = fmaxf(mx, k); mn = fminf(mn, k);
        }
        kmax[tid] = mx; kmin[tid] = mn;
    }
    __syncthreads();
    for (int i = tid; i < ZZ * GG; i += 256) {
        int h = i & 7;
        float qv = qs[i];
        float m = (qv >= 0.f) ? qv * kmax[h] : qv * kmin[h];
        float se = 0.f, av = 0.f;
#pragma unroll 2
        for (int t = 0; t < ZZ; t++) {
            float2 kvv = kv[t * 8 + h];
            float e = __expf(qv * kvv.x - m);
            se += e; av += e * kvv.y;
        }
        os_[i] = av / se;
    }
    __syncthreads();
    if (tid < ZZ) {
        float t8[8];
#pragma unroll
        for (int g = 0; g < 8; g++) {
            float a = bout[g];
#pragma unroll
            for (int kk = 0; kk < 8; kk++) a += os_[tid * 8 + kk] * wout[g * 8 + kk];
            t8[g] = a + xs[tid * 8 + g];
        }
        float mu = 0.f;
#pragma unroll
        for (int g = 0; g < 8; g++) mu += t8[g];
        mu *= 0.125f;
        float var = 0.f;
#pragma unroll
        for (int g = 0; g < 8; g++) { float d = t8[g] - mu; var += d * d; }
        var *= 0.125f;
        float inv = rsqrtf(var + 1e-5f);
#pragma unroll
        for (int g = 0; g < 8; g++)
            g_x[b * (ZZ * GG) + tid * 8 + g] = (t8[g] - mu) * inv * lng[g] + lnb[g];
    }
}

// -------- FFN v8: 64-thread blocks (finer wave quantization), unroll-4 ----
// grid (116, 16): blockIdx.x = row block (128 pairs), blockIdx.y = 128-j chunk.
// 1856 blocks -> per-SM 12/13 (4% tail vs 11.6% at 928 blocks); 16 warps/SM.
__global__ __launch_bounds__(64, 8) void ffn_kernel(int layer) {
    __shared__ float wsm[128 * 36];   // 18.4 KB
    int tid = threadIdx.x;
    int rb = blockIdx.x, jb = blockIdx.y;
    {
        const float4* src = (const float4*)(g_wpk + ((size_t)layer * FFD + jb * 128) * 36);
        float4* dst = (float4*)wsm;
#pragma unroll
        for (int i = 0; i < 18; i++) dst[tid + 64 * i] = src[tid + 64 * i];
    }
    int p0 = rb * 128 + tid;   // pairs p0, p0+64
    u64 X2[2][8], acc[2][8];
#pragma unroll
    for (int s = 0; s < 2; s++) {
        const float4* xv = (const float4*)(g_x + (size_t)(p0 + 64 * s) * 16);
        float4 e0 = xv[0], e1 = xv[1], o0 = xv[2], o1 = xv[3];
        X2[s][0] = pk2(e0.x, o0.x); X2[s][1] = pk2(e0.y, o0.y);
        X2[s][2] = pk2(e0.z, o0.z); X2[s][3] = pk2(e0.w, o0.w);
        X2[s][4] = pk2(e1.x, o1.x); X2[s][5] = pk2(e1.y, o1.y);
        X2[s][6] = pk2(e1.z, o1.z); X2[s][7] = pk2(e1.w, o1.w);
#pragma unroll
        for (int o = 0; o < 8; o++) acc[s][o] = 0ull;
    }
    __syncthreads();

#pragma unroll 4
    for (int jj = 0; jj < 128; jj++) {
        const ulonglong2* w = (const ulonglong2*)(wsm + jj * 36);
        ulonglong2 w10 = w[0], w11 = w[1], w12 = w[2], w13 = w[3];
        u64 bias2 = *(const u64*)(wsm + jj * 36 + 32);
        ulonglong2 w20 = w[4], w21 = w[5], w22 = w[6], w23 = w[7];
#pragma unroll
        for (int s = 0; s < 2; s++) {
            u64 hA = ffma2(X2[s][0], w10.x, bias2);
            u64 hB = ffma2(X2[s][1], w10.y, 0ull);
            hA = ffma2(X2[s][2], w11.x, hA);
            hB = ffma2(X2[s][3], w11.y, hB);
            hA = ffma2(X2[s][4], w12.x, hA);
            hB = ffma2(X2[s][5], w12.y, hB);
            hA = ffma2(X2[s][6], w13.x, hA);
            hB = ffma2(X2[s][7], w13.y, hB);
            u64 ha = relu2(fadd2(hA, hB));
            acc[s][0] = ffma2(ha, w20.x, acc[s][0]);
            acc[s][1] = ffma2(ha, w20.y, acc[s][1]);
            acc[s][2] = ffma2(ha, w21.x, acc[s][2]);
            acc[s][3] = ffma2(ha, w21.y, acc[s][3]);
            acc[s][4] = ffma2(ha, w22.x, acc[s][4]);
            acc[s][5] = ffma2(ha, w22.y, acc[s][5]);
            acc[s][6] = ffma2(ha, w23.x, acc[s][6]);
            acc[s][7] = ffma2(ha, w23.y, acc[s][7]);
        }
    }
#pragma unroll
    for (int s = 0; s < 2; s++) {
        int p = p0 + 64 * s;
        ulonglong2* dst = (ulonglong2*)(g_part64 + ((size_t)jb * NPAIR + p) * 8);
        dst[0] = make_ulonglong2(acc[s][0], acc[s][1]);
        dst[1] = make_ulonglong2(acc[s][2], acc[s][3]);
        dst[2] = make_ulonglong2(acc[s][4], acc[s][5]);
        dst[3] = make_ulonglong2(acc[s][6], acc[s][7]);
    }
}

// -------- head: [finalize last FFN] + concat -> c1 -> c2 -> c3 --------
__global__ void head_kernel(const float* __restrict__ c1_b,
                            const float* __restrict__ c2_w, const float* __restrict__ c2_b,
                            const float* __restrict__ c3_w, const float* __restrict__ c3_b,
                            const float* __restrict__ ff2_b,
                            const float* __restrict__ ln2_g,
                            const float* __restrict__ ln2_b,
                            float* __restrict__ out) {
    __shared__ float cat[8][CATD];
    __shared__ float h1[8][L2D];
    __shared__ float h2[8][8];
    int b0 = blockIdx.x * 8, tid = threadIdx.x;  // 64 threads
    for (int i = tid; i < 8 * L2D; i += 64) {
        int r = i >> 6, c = i & 63;
        cat[r][c] = g_r[(b0 + r) * L2D + c];
    }
    {
        const float* fb = ff2_b + 5 * GG;
        const float* gp = (const float*)g_part64;
        for (int i = tid; i < 8 * ZZ * GG; i += 64) {
            int r = i / (ZZ * GG), sgo = i % (ZZ * GG);
            int s = sgo >> 3, o = sgo & 7;
            int row = (b0 + r) * ZZ + s;
            int p = row >> 1, half = row & 1;
            float v = fb[o] + g_x[(size_t)row * GG + o];
#pragma unroll
            for (int jb = 0; jb < NJB; jb++)
                v += gp[(((size_t)jb * NPAIR + p) * 8 + o) * 2 + half];
            cat[r][64 + sgo] = v;
        }
    }
    __syncthreads();
    {
        const float* lg = ln2_g + 5 * GG;
        const float* lb = ln2_b + 5 * GG;
        for (int i = tid; i < 8 * ZZ; i += 64) {
            int r = i / ZZ, s = i % ZZ;
            float* pr = &cat[r][64 + s * 8];
            float mu = 0.f;
#pragma unroll
            for (int g = 0; g < 8; g++) mu += pr[g];
            mu *= 0.125f;
            float var = 0.f;
#pragma unroll
            for (int g = 0; g < 8; g++) { float d = pr[g] - mu; var += d * d; }
            var *= 0.125f;
            float inv = rsqrtf(var + 1e-5f);
#pragma unroll
            for (int g = 0; g < 8; g++) pr[g] = (pr[g] - mu) * inv * lg[g] + lb[g];
        }
    }
    __syncthreads();
    {
        int j = tid;
        float acc[8];
#pragma unroll
        for (int r = 0; r < 8; r++) acc[r] = 0.f;
#pragma unroll 4
        for (int k = 0; k < CATD; k++) {
            float wv = g_c1t[k * 64 + j];
#pragma unroll
            for (int r = 0; r < 8; r++) acc[r] += cat[r][k] * wv;
        }
        float bv = c1_b[j];
#pragma unroll
        for (int r = 0; r < 8; r++) h1[r][j] = acc[r] + bv;
    }
    __syncthreads();
    {
        int r = tid >> 3, o = tid & 7;
        float a = c2_b[o];
#pragma unroll 4
        for (int k = 0; k < 64; k++) a += h1[r][k] * c2_w[o * 64 + k];
        h2[r][o] = a;
    }
    __syncthreads();
    if (tid < 8) {
        float a = c3_b[0];
#pragma unroll
        for (int k = 0; k < 8; k++) a += h2[tid][k] * c3_w[k];
        out[b0 + tid] = a;
    }
}

extern "C" void kernel_launch(void* const* d_in, const int* in_sizes, int n_in,
                              void* d_out, int out_size) {
    const float* rna    = (const float*)d_in[0];
    const float* drug   = (const float*)d_in[1];
    const float* lin1_w = (const float*)d_in[2];
    const float* lin1_b = (const float*)d_in[3];
    const float* lin2_w = (const float*)d_in[4];
    const float* lin2_b = (const float*)d_in[5];
    const float* chem_w = (const float*)d_in[6];
    const float* pos_w  = (const float*)d_in[7];
    const float* qkv_w  = (const float*)d_in[8];
    const float* qkv_b  = (const float*)d_in[9];
    const float* out_w  = (const float*)d_in[10];
    const float* out_b  = (const float*)d_in[11];
    const float* ln1_g  = (const float*)d_in[12];
    const float* ln1_b  = (const float*)d_in[13];
    const float* ff1_w  = (const float*)d_in[14];
    const float* ff1_b  = (const float*)d_in[15];
    const float* ff2_w  = (const float*)d_in[16];
    const float* ff2_b  = (const float*)d_in[17];
    const float* ln2_g  = (const float*)d_in[18];
    const float* ln2_b  = (const float*)d_in[19];
    const float* c1_w   = (const float*)d_in[20];
    const float* c1_b   = (const float*)d_in[21];
    const float* c2_w   = (const float*)d_in[22];
    const float* c2_b   = (const float*)d_in[23];
    const float* c3_w   = (const float*)d_in[24];
    const float* c3_b   = (const float*)d_in[25];
    float* out = (float*)d_out;

    // Capture slot (4th launch) = embed — first profile since the L-split.
    prep_kernel<<<(PREP_N0 + PREP_N1 + PREP_N2 + PREP_N3 + 255) / 256, 256>>>(
        chem_w, ff1_w, ff1_b, ff2_w, lin1_w, c1_w);
    rna1_kernel<<<64, 256>>>(rna, lin1_b);
    rna2_kernel<<<64, 64>>>(lin2_w, lin2_b);
    embed_kernel<<<dim3(NB, 2), 512>>>(drug);
    for (int i = 0; i < NLY; i++) {
        attn_kernel<<<NB, 256>>>(qkv_w, qkv_b, out_w, out_b, ln1_g, ln1_b,
                                 ff2_b, ln2_g, ln2_b, pos_w, i);
        ffn_kernel<<<dim3(116, NJB), 64>>>(i);
    }
    head_kernel<<<64, 64>>>(c1_b, c2_w, c2_b, c3_w, c3_b,
                            ff2_b, ln2_g, ln2_b, out);
}

// round 17
// speedup vs baseline: 1.4519x; 1.4519x over previous
#include <cuda_runtime.h>

#define NB 512
#define LL 2713
#define ZZ 58
#define GG 8
#define FFD 2048
#define NLY 6
#define RNAIN 1018
#define L1D 256
#define L2D 64
#define CATD 528
#define NPAIR 14848   // 29696 rows / 2
#define NJB 16        // j chunks (128 j each)

typedef unsigned long long u64;

// -------- scratch (device globals; no allocations allowed) --------
__device__ float g_r1[NB * L1D];
__device__ float g_r[NB * L2D];
__device__ float g_x[NB * ZZ * GG];
__device__ float g_chemt[LL * GG];             // chem_w transposed [l][g]
__device__ float g_wpk[NLY * FFD * 36];        // per j: w1-dup x16 | w2-dup x16 | b1-dup x2 | pad2
__device__ float g_l1t[RNAIN * L1D];           // lin1_w transposed [k][j]
__device__ float g_c1t[CATD * 64];             // c1_w transposed [k][j]
__device__ u64   g_part64[NJB * NPAIR * 8];    // ffn partials [jb][pair][o] as f32x2

// -------- packed f32x2 helpers (FFMA2 path ptxas won't emit from C++) ------
__device__ __forceinline__ u64 pk2(float lo, float hi) {
    u64 d; asm("mov.b64 %0,{%1,%2};" : "=l"(d) : "f"(lo), "f"(hi)); return d;
}
__device__ __forceinline__ void upk2(u64 d, float& lo, float& hi) {
    asm("mov.b64 {%0,%1},%2;" : "=f"(lo), "=f"(hi) : "l"(d));
}
__device__ __forceinline__ u64 ffma2(u64 a, u64 b, u64 c) {
    u64 d; asm("fma.rn.f32x2 %0,%1,%2,%3;" : "=l"(d) : "l"(a), "l"(b), "l"(c)); return d;
}
__device__ __forceinline__ u64 fadd2(u64 a, u64 b) {
    u64 d; asm("add.rn.f32x2 %0,%1,%2;" : "=l"(d) : "l"(a), "l"(b)); return d;
}
__device__ __forceinline__ u64 relu2(u64 a) {
    float h0, h1; upk2(a, h0, h1);
    return pk2(fmaxf(h0, 0.f), fmaxf(h1, 0.f));
}

// -------- prep: transposes / weight packing (cheap, once per graph) --------
#define PREP_N0 (LL * GG)
#define PREP_N1 (NLY * FFD * 36)
#define PREP_N2 (RNAIN * L1D)
#define PREP_N3 (CATD * 64)
__global__ void prep_kernel(const float* __restrict__ chem_w,
                            const float* __restrict__ ff1_w,
                            const float* __restrict__ ff1_b,
                            const float* __restrict__ ff2_w,
                            const float* __restrict__ lin1_w,
                            const float* __restrict__ c1_w) {
    int i = blockIdx.x * blockDim.x + threadIdx.x;
    if (i < PREP_N0) {
        int l = i / GG, g = i % GG;
        g_chemt[i] = chem_w[g * LL + l];
    }
    int n = i - PREP_N0;
    if (n >= 0 && n < PREP_N1) {
        int ly = n / (FFD * 36);
        int rem = n % (FFD * 36);
        int j = rem / 36, s = rem % 36;
        float v = 0.f;
        if (s < 16)      v = ff1_w[(ly * FFD + j) * GG + (s >> 1)];
        else if (s < 32) v = ff2_w[(ly * GG + ((s - 16) >> 1)) * FFD + j];
        else if (s < 34) v = ff1_b[ly * FFD + j];
        g_wpk[n] = v;
    }
    int n2 = n - PREP_N1;
    if (n2 >= 0 && n2 < PREP_N2) {
        int k = n2 / L1D, j = n2 % L1D;
        g_l1t[n2] = lin1_w[j * RNAIN + k];
    }
    int n3 = n2 - PREP_N2;
    if (n3 >= 0 && n3 < PREP_N3) {
        int k = n3 / 64, j = n3 % 64;
        g_c1t[n3] = c1_w[j * CATD + k];
    }
}

// -------- rna branch (coalesced via transposed weights) --------
__global__ void rna1_kernel(const float* __restrict__ rna,
                            const float* __restrict__ bias) {
    __shared__ float xs[8][RNAIN];
    int b0 = blockIdx.x * 8;
    for (int i = threadIdx.x; i < 8 * RNAIN; i += 256)
        (&xs[0][0])[i] = rna[b0 * RNAIN + i];
    __syncthreads();
    int j = threadIdx.x;
    float acc[8];
#pragma unroll
    for (int r = 0; r < 8; r++) acc[r] = 0.f;
#pragma unroll 2
    for (int k = 0; k < RNAIN; k++) {
        float wv = g_l1t[k * L1D + j];
#pragma unroll
        for (int r = 0; r < 8; r++) acc[r] += xs[r][k] * wv;
    }
    float bv = bias[j];
#pragma unroll
    for (int r = 0; r < 8; r++) g_r1[(b0 + r) * L1D + j] = acc[r] + bv;
}

__global__ void rna2_kernel(const float* __restrict__ w,
                            const float* __restrict__ bias) {
    __shared__ float xs[8][L1D];
    int b0 = blockIdx.x * 8;
    for (int i = threadIdx.x; i < 8 * L1D; i += 64)
        (&xs[0][0])[i] = g_r1[b0 * L1D + i];
    __syncthreads();
    int j = threadIdx.x;
    float acc[8];
#pragma unroll
    for (int r = 0; r < 8; r++) acc[r] = 0.f;
    const float* wr = w + j * L1D;
#pragma unroll 4
    for (int k = 0; k < L1D; k++) {
        float wv = wr[k];
#pragma unroll
        for (int r = 0; r < 8; r++) acc[r] += xs[r][k] * wv;
    }
    float bv = bias[j];
#pragma unroll
    for (int r = 0; r < 8; r++) g_r[(b0 + r) * L2D + j] = acc[r] + bv;
}

// -------- embedding (R8-exact, best measured 85us): non-split, depth-8 ----
__global__ __launch_bounds__(512, 2) void embed_kernel(const float* __restrict__ drug,
                                                       const float* __restrict__ pos_w) {
    __shared__ float red[8][ZZ * GG];
    int b = blockIdx.x, tid = threadIdx.x;
    int warp = tid >> 5, lane = tid & 31;
    const float* dbase = drug + (long)b * (LL * ZZ);
    bool act = lane < 29;
    int zoff = act ? 2 * lane : 54;   // clamp: inactive lanes load valid addr, discard
    u64 acc[2][4];
#pragma unroll
    for (int zi = 0; zi < 2; zi++)
#pragma unroll
        for (int gp = 0; gp < 4; gp++) acc[zi][gp] = 0ull;

    // main: 21 iterations of 8 batched rows (covers l in [0, 2688))
    for (int it = 0; it < 21; it++) {
        int l0 = warp + 128 * it;
        float2 d[8];
#pragma unroll
        for (int k = 0; k < 8; k++)
            d[k] = *(const float2*)(dbase + (l0 + 16 * k) * ZZ + zoff);
#pragma unroll
        for (int k = 0; k < 8; k++) {
            const ulonglong2* crow = (const ulonglong2*)(g_chemt + (l0 + 16 * k) * GG);
            ulonglong2 cA = crow[0], cB = crow[1];
            u64 d0 = pk2(d[k].x, d[k].x), d1 = pk2(d[k].y, d[k].y);
            acc[0][0] = ffma2(cA.x, d0, acc[0][0]);
            acc[0][1] = ffma2(cA.y, d0, acc[0][1]);
            acc[0][2] = ffma2(cB.x, d0, acc[0][2]);
            acc[0][3] = ffma2(cB.y, d0, acc[0][3]);
            acc[1][0] = ffma2(cA.x, d1, acc[1][0]);
            acc[1][1] = ffma2(cA.y, d1, acc[1][1]);
            acc[1][2] = ffma2(cB.x, d1, acc[1][2]);
            acc[1][3] = ffma2(cB.y, d1, acc[1][3]);
        }
    }
    // tail rows [2688, 2713)
    for (int l = 2688 + warp; l < LL; l += 16) {
        float2 d = *(const float2*)(dbase + l * ZZ + zoff);
        const ulonglong2* crow = (const ulonglong2*)(g_chemt + l * GG);
        ulonglong2 cA = crow[0], cB = crow[1];
        u64 d0 = pk2(d.x, d.x), d1 = pk2(d.y, d.y);
        acc[0][0] = ffma2(cA.x, d0, acc[0][0]);
        acc[0][1] = ffma2(cA.y, d0, acc[0][1]);
        acc[0][2] = ffma2(cB.x, d0, acc[0][2]);
        acc[0][3] = ffma2(cB.y, d0, acc[0][3]);
        acc[1][0] = ffma2(cA.x, d1, acc[1][0]);
        acc[1][1] = ffma2(cA.y, d1, acc[1][1]);
        acc[1][2] = ffma2(cB.x, d1, acc[1][2]);
        acc[1][3] = ffma2(cB.y, d1, acc[1][3]);
    }
    // two-stage cross-warp reduction (16 warps -> 8 -> scalar)
    if (warp >= 8 && act) {
#pragma unroll
        for (int zi = 0; zi < 2; zi++)
#pragma unroll
            for (int gp = 0; gp < 4; gp++)
                *(u64*)&red[warp - 8][(2 * lane + zi) * GG + 2 * gp] = acc[zi][gp];
    }
    __syncthreads();
    if (warp < 8 && act) {
#pragma unroll
        for (int zi = 0; zi < 2; zi++)
#pragma unroll
            for (int gp = 0; gp < 4; gp++)
                acc[zi][gp] = fadd2(acc[zi][gp], *(u64*)&red[warp][(2 * lane + zi) * GG + 2 * gp]);
    }
    __syncthreads();
    if (warp < 8 && act) {
#pragma unroll
        for (int zi = 0; zi < 2; zi++)
#pragma unroll
            for (int gp = 0; gp < 4; gp++)
                *(u64*)&red[warp][(2 * lane + zi) * GG + 2 * gp] = acc[zi][gp];
    }
    __syncthreads();
    if (tid < ZZ * GG) {
        int z = tid >> 3, g = tid & 7;
        float s = pos_w[g * ZZ + z];
#pragma unroll
        for (int w = 0; w < 8; w++) s += red[w][tid];
        g_x[b * (ZZ * GG) + tid] = s;
    }
}

// -------- attention layer: [finalize prev FFN] + qkv + softmax + out + LN1 --
__global__ __launch_bounds__(256) void attn_kernel(const float* __restrict__ qkv_w,
                            const float* __restrict__ qkv_b,
                            const float* __restrict__ out_w,
                            const float* __restrict__ out_b,
                            const float* __restrict__ ln_g,
                            const float* __restrict__ ln_b,
                            const float* __restrict__ ff2_b,
                            const float* __restrict__ ln2_g,
                            const float* __restrict__ ln2_b, int layer) {
    qkv_w += layer * 24 * GG; qkv_b += layer * 24;
    out_w += layer * GG * GG; out_b += layer * GG;
    ln_g += layer * GG; ln_b += layer * GG;
    __shared__ float xs[ZZ * GG], qs[ZZ * GG], os_[ZZ * GG];
    __shared__ float2 kv[ZZ * GG];
    __shared__ float wqkvT[GG * 24], bqkv[24], wout[GG * GG], bout[GG], lng[GG], lnb[GG];
    __shared__ float kmax[GG], kmin[GG];
    int b = blockIdx.x, tid = threadIdx.x;
    if (tid < 192) { int j = tid / 8, kk = tid % 8; wqkvT[kk * 24 + j] = qkv_w[tid]; }
    if (tid < 24) bqkv[tid] = qkv_b[tid];
    if (tid < 64) wout[tid] = out_w[tid];
    if (tid < 8) { bout[tid] = out_b[tid]; lng[tid] = ln_g[tid]; lnb[tid] = ln_b[tid]; }

    if (layer > 0) {
        const float* fb  = ff2_b + (layer - 1) * GG;
        const float* gp  = (const float*)g_part64;
        for (int i = tid; i < ZZ * GG; i += 256) {
            int s = i >> 3, o = i & 7;
            int p = b * 29 + (s >> 1), half = s & 1;
            float v = fb[o] + g_x[b * (ZZ * GG) + i];
#pragma unroll
            for (int jb = 0; jb < NJB; jb++)
                v += gp[(((size_t)jb * NPAIR + p) * 8 + o) * 2 + half];
            xs[i] = v;
        }
        __syncthreads();
        const float* lg2 = ln2_g + (layer - 1) * GG;
        const float* lb2 = ln2_b + (layer - 1) * GG;
        if (tid < ZZ) {
            float* pr = xs + tid * 8;
            float mu = 0.f;
#pragma unroll
            for (int g = 0; g < 8; g++) mu += pr[g];
            mu *= 0.125f;
            float var = 0.f;
#pragma unroll
            for (int g = 0; g < 8; g++) { float d = pr[g] - mu; var += d * d; }
            var *= 0.125f;
            float inv = rsqrtf(var + 1e-5f);
#pragma unroll
            for (int g = 0; g < 8; g++) pr[g] = (pr[g] - mu) * inv * lg2[g] + lb2[g];
        }
    } else {
        for (int i = tid; i < ZZ * GG; i += 256) xs[i] = g_x[b * (ZZ * GG) + i];
    }
    __syncthreads();
    for (int i = tid; i < ZZ * 24; i += 256) {
        int zz = i / 24, j = i % 24;
        float a = bqkv[j];
#pragma unroll
        for (int kk = 0; kk < 8; kk++) a += xs[zz * 8 + kk] * wqkvT[kk * 24 + j];
        if (j < 8) qs[zz * 8 + j] = a;
        else if (j < 16) kv[zz * 8 + (j - 8)].x = a;
        else kv[zz * 8 + (j - 16)].y = a;
    }
    __syncthreads();
    if (tid < 8) {
        float mx = -1e30f, mn = 1e30f;
        for (int t = 0; t < ZZ; t++) {
            float k = kv[t * 8 + tid].x;
            mx = fmaxf(mx, k); mn = fminf(mn, k);
        }
        kmax[tid] = mx; kmin[tid] = mn;
    }
    __syncthreads();
    for (int i = tid; i < ZZ * GG; i += 256) {
        int h = i & 7;
        float qv = qs[i];
        float m = (qv >= 0.f) ? qv * kmax[h] : qv * kmin[h];
        float se = 0.f, av = 0.f;
#pragma unroll 2
        for (int t = 0; t < ZZ; t++) {
            float2 kvv = kv[t * 8 + h];
            float e = __expf(qv * kvv.x - m);
            se += e; av += e * kvv.y;
        }
        os_[i] = av / se;
    }
    __syncthreads();
    if (tid < ZZ) {
        float t8[8];
#pragma unroll
        for (int g = 0; g < 8; g++) {
            float a = bout[g];
#pragma unroll
            for (int kk = 0; kk < 8; kk++) a += os_[tid * 8 + kk] * wout[g * 8 + kk];
            t8[g] = a + xs[tid * 8 + g];
        }
        float mu = 0.f;
#pragma unroll
        for (int g = 0; g < 8; g++) mu += t8[g];
        mu *= 0.125f;
        float var = 0.f;
#pragma unroll
        for (int g = 0; g < 8; g++) { float d = t8[g] - mu; var += d * d; }
        var *= 0.125f;
        float inv = rsqrtf(var + 1e-5f);
#pragma unroll
        for (int g = 0; g < 8; g++)
            g_x[b * (ZZ * GG) + tid * 8 + g] = (t8[g] - mu) * inv * lng[g] + lnb[g];
    }
}

// -------- FFN v7 (R15-exact, best measured 53.5us/layer) --------
__global__ __launch_bounds__(128, 4) void ffn_kernel(int layer) {
    __shared__ float wsm[128 * 36];   // 18.4 KB
    int tid = threadIdx.x;
    int rb = blockIdx.x, jb = blockIdx.y;
    {
        const float4* src = (const float4*)(g_wpk + ((size_t)layer * FFD + jb * 128) * 36);
        float4* dst = (float4*)wsm;
#pragma unroll
        for (int i = 0; i < 9; i++) dst[tid + 128 * i] = src[tid + 128 * i];
    }
    int p0 = rb * 256 + tid;   // pairs p0, p0+128
    u64 X2[2][8], acc[2][8];
#pragma unroll
    for (int s = 0; s < 2; s++) {
        const float4* xv = (const float4*)(g_x + (size_t)(p0 + 128 * s) * 16);
        float4 e0 = xv[0], e1 = xv[1], o0 = xv[2], o1 = xv[3];
        X2[s][0] = pk2(e0.x, o0.x); X2[s][1] = pk2(e0.y, o0.y);
        X2[s][2] = pk2(e0.z, o0.z); X2[s][3] = pk2(e0.w, o0.w);
        X2[s][4] = pk2(e1.x, o1.x); X2[s][5] = pk2(e1.y, o1.y);
        X2[s][6] = pk2(e1.z, o1.z); X2[s][7] = pk2(e1.w, o1.w);
#pragma unroll
        for (int o = 0; o < 8; o++) acc[s][o] = 0ull;
    }
    __syncthreads();

#pragma unroll 4
    for (int jj = 0; jj < 128; jj++) {
        const ulonglong2* w = (const ulonglong2*)(wsm + jj * 36);
        ulonglong2 w10 = w[0], w11 = w[1], w12 = w[2], w13 = w[3];
        u64 bias2 = *(const u64*)(wsm + jj * 36 + 32);
        ulonglong2 w20 = w[4], w21 = w[5], w22 = w[6], w23 = w[7];
#pragma unroll
        for (int s = 0; s < 2; s++) {
            u64 hA = ffma2(X2[s][0], w10.x, bias2);
            u64 hB = ffma2(X2[s][1], w10.y, 0ull);
            hA = ffma2(X2[s][2], w11.x, hA);
            hB = ffma2(X2[s][3], w11.y, hB);
            hA = ffma2(X2[s][4], w12.x, hA);
            hB = ffma2(X2[s][5], w12.y, hB);
            hA = ffma2(X2[s][6], w13.x, hA);
            hB = ffma2(X2[s][7], w13.y, hB);
            u64 ha = relu2(fadd2(hA, hB));
            acc[s][0] = ffma2(ha, w20.x, acc[s][0]);
            acc[s][1] = ffma2(ha, w20.y, acc[s][1]);
            acc[s][2] = ffma2(ha, w21.x, acc[s][2]);
            acc[s][3] = ffma2(ha, w21.y, acc[s][3]);
            acc[s][4] = ffma2(ha, w22.x, acc[s][4]);
            acc[s][5] = ffma2(ha, w22.y, acc[s][5]);
            acc[s][6] = ffma2(ha, w23.x, acc[s][6]);
            acc[s][7] = ffma2(ha, w23.y, acc[s][7]);
        }
    }
#pragma unroll
    for (int s = 0; s < 2; s++) {
        int p = p0 + 128 * s;
        ulonglong2* dst = (ulonglong2*)(g_part64 + ((size_t)jb * NPAIR + p) * 8);
        dst[0] = make_ulonglong2(acc[s][0], acc[s][1]);
        dst[1] = make_ulonglong2(acc[s][2], acc[s][3]);
        dst[2] = make_ulonglong2(acc[s][4], acc[s][5]);
        dst[3] = make_ulonglong2(acc[s][6], acc[s][7]);
    }
}

// -------- head: [finalize last FFN] + concat -> c1 -> c2 -> c3 --------
__global__ void head_kernel(const float* __restrict__ c1_b,
                            const float* __restrict__ c2_w, const float* __restrict__ c2_b,
                            const float* __restrict__ c3_w, const float* __restrict__ c3_b,
                            const float* __restrict__ ff2_b,
                            const float* __restrict__ ln2_g,
                            const float* __restrict__ ln2_b,
                            float* __restrict__ out) {
    __shared__ float cat[8][CATD];
    __shared__ float h1[8][L2D];
    __shared__ float h2[8][8];
    int b0 = blockIdx.x * 8, tid = threadIdx.x;  // 64 threads
    for (int i = tid; i < 8 * L2D; i += 64) {
        int r = i >> 6, c = i & 63;
        cat[r][c] = g_r[(b0 + r) * L2D + c];
    }
    {
        const float* fb = ff2_b + 5 * GG;
        const float* gp = (const float*)g_part64;
        for (int i = tid; i < 8 * ZZ * GG; i += 64) {
            int r = i / (ZZ * GG), sgo = i % (ZZ * GG);
            int s = sgo >> 3, o = sgo & 7;
            int row = (b0 + r) * ZZ + s;
            int p = row >> 1, half = row & 1;
            float v = fb[o] + g_x[(size_t)row * GG + o];
#pragma unroll
            for (int jb = 0; jb < NJB; jb++)
                v += gp[(((size_t)jb * NPAIR + p) * 8 + o) * 2 + half];
            cat[r][64 + sgo] = v;
        }
    }
    __syncthreads();
    {
        const float* lg = ln2_g + 5 * GG;
        const float* lb = ln2_b + 5 * GG;
        for (int i = tid; i < 8 * ZZ; i += 64) {
            int r = i / ZZ, s = i % ZZ;
            float* pr = &cat[r][64 + s * 8];
            float mu = 0.f;
#pragma unroll
            for (int g = 0; g < 8; g++) mu += pr[g];
            mu *= 0.125f;
            float var = 0.f;
#pragma unroll
            for (int g = 0; g < 8; g++) { float d = pr[g] - mu; var += d * d; }
            var *= 0.125f;
            float inv = rsqrtf(var + 1e-5f);
#pragma unroll
            for (int g = 0; g < 8; g++) pr[g] = (pr[g] - mu) * inv * lg[g] + lb[g];
        }
    }
    __syncthreads();
    {
        int j = tid;
        float acc[8];
#pragma unroll
        for (int r = 0; r < 8; r++) acc[r] = 0.f;
#pragma unroll 4
        for (int k = 0; k < CATD; k++) {
            float wv = g_c1t[k * 64 + j];
#pragma unroll
            for (int r = 0; r < 8; r++) acc[r] += cat[r][k] * wv;
        }
        float bv = c1_b[j];
#pragma unroll
        for (int r = 0; r < 8; r++) h1[r][j] = acc[r] + bv;
    }
    __syncthreads();
    {
        int r = tid >> 3, o = tid & 7;
        float a = c2_b[o];
#pragma unroll 4
        for (int k = 0; k < 64; k++) a += h1[r][k] * c2_w[o * 64 + k];
        h2[r][o] = a;
    }
    __syncthreads();
    if (tid < 8) {
        float a = c3_b[0];
#pragma unroll
        for (int k = 0; k < 8; k++) a += h2[tid][k] * c3_w[k];
        out[b0 + tid] = a;
    }
}

extern "C" void kernel_launch(void* const* d_in, const int* in_sizes, int n_in,
                              void* d_out, int out_size) {
    const float* rna    = (const float*)d_in[0];
    const float* drug   = (const float*)d_in[1];
    const float* lin1_w = (const float*)d_in[2];
    const float* lin1_b = (const float*)d_in[3];
    const float* lin2_w = (const float*)d_in[4];
    const float* lin2_b = (const float*)d_in[5];
    const float* chem_w = (const float*)d_in[6];
    const float* pos_w  = (const float*)d_in[7];
    const float* qkv_w  = (const float*)d_in[8];
    const float* qkv_b  = (const float*)d_in[9];
    const float* out_w  = (const float*)d_in[10];
    const float* out_b  = (const float*)d_in[11];
    const float* ln1_g  = (const float*)d_in[12];
    const float* ln1_b  = (const float*)d_in[13];
    const float* ff1_w  = (const float*)d_in[14];
    const float* ff1_b  = (const float*)d_in[15];
    const float* ff2_w  = (const float*)d_in[16];
    const float* ff2_b  = (const float*)d_in[17];
    const float* ln2_g  = (const float*)d_in[18];
    const float* ln2_b  = (const float*)d_in[19];
    const float* c1_w   = (const float*)d_in[20];
    const float* c1_b   = (const float*)d_in[21];
    const float* c2_w   = (const float*)d_in[22];
    const float* c2_b   = (const float*)d_in[23];
    const float* c3_w   = (const float*)d_in[24];
    const float* c3_b   = (const float*)d_in[25];
    float* out = (float*)d_out;

    // Capture slot (4th launch) = embed — verify the revert lands back at ~85us.
    prep_kernel<<<(PREP_N0 + PREP_N1 + PREP_N2 + PREP_N3 + 255) / 256, 256>>>(
        chem_w, ff1_w, ff1_b, ff2_w, lin1_w, c1_w);
    rna1_kernel<<<64, 256>>>(rna, lin1_b);
    rna2_kernel<<<64, 64>>>(lin2_w, lin2_b);
    embed_kernel<<<NB, 512>>>(drug, pos_w);
    for (int i = 0; i < NLY; i++) {
        attn_kernel<<<NB, 256>>>(qkv_w, qkv_b, out_w, out_b, ln1_g, ln1_b,
                                 ff2_b, ln2_g, ln2_b, i);
        ffn_kernel<<<dim3(58, NJB), 128>>>(i);
    }
    head_kernel<<<64, 64>>>(c1_b, c2_w, c2_b, c3_w, c3_b,
                            ff2_b, ln2_g, ln2_b, out);
}